// round 5
// baseline (speedup 1.0000x reference)
#include <cuda_runtime.h>
#include <math.h>
#include <stdint.h>

// Problem constants
#define NN 20000
#define EE 320000
#define RR 100
#define FF 256
#define HH 8
#define DD 32
#define FHID 1024
#define PF 768            // packed projection stride (fh|ftl|fen)
#define ALPHA 0.1f
#define SLOPE 0.2f

// ---------------------------------------------------------------------------
__device__ __forceinline__ uint32_t smem_u32(const void* p) {
    uint32_t a;
    asm("{ .reg .u64 t; cvta.to.shared.u64 t, %1; cvt.u32.u64 %0, t; }" : "=r"(a) : "l"(p));
    return a;
}
#define CP_ASYNC16(dst, src) \
    asm volatile("cp.async.cg.shared.global [%0], [%1], 16;" :: "r"(dst), "l"(src) : "memory")
#define CP_COMMIT() asm volatile("cp.async.commit_group;" ::: "memory")
#define CP_WAIT(n)  asm volatile("cp.async.wait_group %0;" :: "n"(n) : "memory")

#define LDSM_X4(r0, r1, r2, r3, addr) \
    asm volatile("ldmatrix.sync.aligned.m8n8.x4.shared.b16 {%0,%1,%2,%3}, [%4];" \
                 : "=r"(r0), "=r"(r1), "=r"(r2), "=r"(r3) : "r"(addr))
#define MMA_TF32(c, a, b) \
    asm volatile("mma.sync.aligned.m16n8k8.row.col.f32.tf32.tf32.f32 " \
                 "{%0,%1,%2,%3},{%4,%5,%6,%7},{%8,%9},{%0,%1,%2,%3};" \
                 : "+f"((c)[0]), "+f"((c)[1]), "+f"((c)[2]), "+f"((c)[3]) \
                 : "r"((a)[0]), "r"((a)[1]), "r"((a)[2]), "r"((a)[3]), \
                   "r"((b)[0]), "r"((b)[1]))

__device__ __forceinline__ float tf32_rnd(float x) {
    uint32_t u = __float_as_uint(x), o;
    asm("cvt.rna.tf32.f32 %0, %1;" : "=r"(o) : "r"(u));
    return __uint_as_float(o);
}

// ------------------------- scratch (device globals) -------------------------
__device__ float g_xln[NN * FF];
__device__ float g_proj[NN * PF];      // [fh | ftl | fen] packed per row
__device__ float g_rln[RR * FF];
__device__ float g_fr [RR * FF];
__device__ int   g_cnt [NN];
__device__ int   g_fill[NN];
__device__ int   g_rowptr[NN + 1];
__device__ int   g_srcs[EE];
__device__ int   g_rids[EE];
__device__ float g_e[EE * HH];
__device__ float g_a[EE * HH];
__device__ float g_fa[NN * FF];
__device__ float g_fb[NN * FF];
__device__ float g_rst[NN * FF];
__device__ float g_y  [NN * FF];
__device__ float g_hid[NN * FHID];
__device__ float g_wcatT[PF * FF];     // K-major [768,256]: Whead|Wtail|Went rows
__device__ float g_wrelT [FF * FF];
__device__ float g_w1T[FHID * FF];
__device__ float g_w2T[FF * FHID];

// ------------------------- LayerNorm (outputs tf32-rounded) -------------------
__global__ void ln_kernel(const float* __restrict__ in, float* __restrict__ out,
                          const float* __restrict__ gam, const float* __restrict__ bet) {
    int row = blockIdx.x;
    int t = threadIdx.x;
    float x = in[row * FF + t];
    float s = x, s2 = x * x;
    #pragma unroll
    for (int o = 16; o; o >>= 1) {
        s  += __shfl_xor_sync(0xffffffffu, s,  o);
        s2 += __shfl_xor_sync(0xffffffffu, s2, o);
    }
    __shared__ float rs[8], rs2[8];
    int w = t >> 5, l = t & 31;
    if (l == 0) { rs[w] = s; rs2[w] = s2; }
    __syncthreads();
    s = 0.f; s2 = 0.f;
    #pragma unroll
    for (int i = 0; i < 8; i++) { s += rs[i]; s2 += rs2[i]; }
    float m = s * (1.0f / FF);
    float var = s2 * (1.0f / FF) - m * m;
    float inv = rsqrtf(var + 1e-5f);
    out[row * FF + t] = tf32_rnd((x - m) * inv * gam[t] + bet[t]);
}

// ------------------------- weight transpose (+tf32 round) --------------------
__global__ void transpose_rnd(const float* __restrict__ B, float* __restrict__ BT,
                              int K, int N) {
    __shared__ float t[32][33];
    int n0 = blockIdx.x * 32, k0 = blockIdx.y * 32;
    int x = threadIdx.x, y = threadIdx.y;
    #pragma unroll
    for (int r = 0; r < 32; r += 8)
        t[y + r][x] = B[(size_t)(k0 + y + r) * N + n0 + x];
    __syncthreads();
    #pragma unroll
    for (int r = 0; r < 32; r += 8)
        BT[(size_t)(n0 + y + r) * K + k0 + x] = tf32_rnd(t[x][y + r]);
}
__global__ void transpose4_rnd(const float* __restrict__ Wh, const float* __restrict__ Wt,
                               const float* __restrict__ We, const float* __restrict__ Wr,
                               float* __restrict__ wcat, float* __restrict__ wrel) {
    __shared__ float t[32][33];
    int z = blockIdx.z;
    const float* B = (z == 0) ? Wh : (z == 1) ? Wt : (z == 2) ? We : Wr;
    float* BT = (z < 3) ? (wcat + (size_t)z * FF * FF) : wrel;
    int n0 = blockIdx.x * 32, k0 = blockIdx.y * 32;
    int x = threadIdx.x, y = threadIdx.y;
    #pragma unroll
    for (int r = 0; r < 32; r += 8)
        t[y + r][x] = B[(size_t)(k0 + y + r) * FF + n0 + x];
    __syncthreads();
    #pragma unroll
    for (int r = 0; r < 32; r += 8)
        BT[(size_t)(n0 + y + r) * FF + k0 + x] = tf32_rnd(t[x][y + r]);
}

// ------------------------- tf32 mma.sync GEMM --------------------------------
// C[M,Nc] = A[M,K] @ BT[Nc,K]^T (+bias) (relu if mode&1) (tf32-round if mode&2)
// (+res if res != null).
// 128x128 block tile, BK=32, 3-stage cp.async, 4 warps (2x2), warp tile 64x64.
#define GSTAGES 3
#define GSTG 32768
#define GSMEM_BYTES (GSTAGES * GSTG)

__global__ void __launch_bounds__(128, 2)
mma_gemm(const float* __restrict__ A, const float* __restrict__ BT,
         float* __restrict__ C, int M, int Nc, int K,
         const float* __restrict__ bias, const float* __restrict__ res, int mode) {
    extern __shared__ float smemf[];
    const uint32_t sb = smem_u32(smemf);

    const int m0 = blockIdx.y * 128;
    const int n0 = blockIdx.x * 128;
    const int tid = threadIdx.x;
    const int warp = tid >> 5, lane = tid & 31;
    const int wm = warp >> 1, wn = warp & 1;          // 2 x 2 warps, 64x64 each

    // ---- async loads: each thread owns one full 128B row of A and of B ----
    int aRow = m0 + tid; if (aRow >= M) aRow = M - 1;
    const float* aG = A + (size_t)aRow * K;
    const float* bG = BT + (size_t)(n0 + tid) * K;
    const uint32_t sA = sb + (uint32_t)tid * 128;
    const uint32_t sB = sb + 16384 + (uint32_t)tid * 128;
    uint32_t swz[8];
    #pragma unroll
    for (int j = 0; j < 8; j++)
        swz[j] = (uint32_t)((j ^ (tid & 7)) << 4);

    const int nCh = K >> 5;

    float c[4][8][4];
    #pragma unroll
    for (int mt = 0; mt < 4; mt++)
        #pragma unroll
        for (int nt = 0; nt < 8; nt++)
            #pragma unroll
            for (int q = 0; q < 4; q++) c[mt][nt][q] = 0.f;

    // prologue: stages 0 and 1
    #pragma unroll
    for (int s = 0; s < 2; s++) {
        const uint32_t off = (uint32_t)s * GSTG;
        const float* ag = aG + s * 32;
        const float* bg = bG + s * 32;
        #pragma unroll
        for (int j = 0; j < 8; j++) CP_ASYNC16(sA + off + swz[j], ag + j * 4);
        #pragma unroll
        for (int j = 0; j < 8; j++) CP_ASYNC16(sB + off + swz[j], bg + j * 4);
        CP_COMMIT();
    }

    const int q8 = lane >> 3, r8 = lane & 7;

    for (int i = 0; i < nCh; i++) {
        __syncthreads();                     // WAR: stage (i+2)%3 free
        if (i + 2 < nCh) {
            const uint32_t off = (uint32_t)((i + 2) % GSTAGES) * GSTG;
            const float* ag = aG + (i + 2) * 32;
            const float* bg = bG + (i + 2) * 32;
            #pragma unroll
            for (int j = 0; j < 8; j++) CP_ASYNC16(sA + off + swz[j], ag + j * 4);
            #pragma unroll
            for (int j = 0; j < 8; j++) CP_ASYNC16(sB + off + swz[j], bg + j * 4);
        }
        CP_COMMIT();                          // constant group count per iter
        CP_WAIT(2);                           // chunk i resident
        __syncthreads();

        const uint32_t Ab = sb + (uint32_t)(i % GSTAGES) * GSTG;
        const uint32_t Bb = Ab + 16384;
        #pragma unroll
        for (int ks = 0; ks < 4; ks++) {
            uint32_t a[4][4];
            #pragma unroll
            for (int mt = 0; mt < 4; mt++) {
                const int rl = wm * 64 + mt * 16 + (q8 & 1) * 8 + r8;
                const int kc = ks * 2 + (q8 >> 1);
                const uint32_t ad = Ab + (uint32_t)rl * 128 + (uint32_t)((kc ^ (rl & 7)) << 4);
                LDSM_X4(a[mt][0], a[mt][1], a[mt][2], a[mt][3], ad);
            }
            uint32_t b[8][2];
            #pragma unroll
            for (int ntp = 0; ntp < 4; ntp++) {
                const int nl = wn * 64 + ntp * 16 + (q8 >> 1) * 8 + r8;
                const int kc = ks * 2 + (q8 & 1);
                const uint32_t bd = Bb + (uint32_t)nl * 128 + (uint32_t)((kc ^ (nl & 7)) << 4);
                LDSM_X4(b[ntp * 2][0], b[ntp * 2][1], b[ntp * 2 + 1][0], b[ntp * 2 + 1][1], bd);
            }
            #pragma unroll
            for (int mt = 0; mt < 4; mt++)
                #pragma unroll
                for (int nt = 0; nt < 8; nt++)
                    MMA_TF32(c[mt][nt], a[mt], b[nt]);
        }
    }

    // ---- epilogue ----
    const int g = lane >> 2, t4 = lane & 3;
    #pragma unroll
    for (int mt = 0; mt < 4; mt++) {
        #pragma unroll
        for (int half = 0; half < 2; half++) {
            const int m = m0 + wm * 64 + mt * 16 + g + half * 8;
            if (m < M) {
                float* cRow = C + (size_t)m * Nc + n0 + wn * 64;
                const float* rRow = res ? (res + (size_t)m * Nc + n0 + wn * 64) : nullptr;
                #pragma unroll
                for (int nt = 0; nt < 8; nt++) {
                    const int colb = nt * 8 + 2 * t4;
                    float v0 = c[mt][nt][half * 2 + 0];
                    float v1 = c[mt][nt][half * 2 + 1];
                    if (bias) {
                        const float* bp = bias + n0 + wn * 64 + colb;
                        v0 += bp[0]; v1 += bp[1];
                    }
                    if (mode & 1) { v0 = fmaxf(v0, 0.f); v1 = fmaxf(v1, 0.f); }
                    if (mode & 2) { v0 = tf32_rnd(v0); v1 = tf32_rnd(v1); }
                    if (rRow) { v0 += rRow[colb]; v1 += rRow[colb + 1]; }
                    float2 v; v.x = v0; v.y = v1;
                    *(float2*)(cRow + colb) = v;
                }
            }
        }
    }
}

// ------------------------- CSR build -----------------------------------------
__global__ void zero_kernel() {
    int i = blockIdx.x * blockDim.x + threadIdx.x;
    if (i < NN) { g_cnt[i] = 0; g_fill[i] = 0; }
}
__global__ void count_kernel(const int* __restrict__ dst) {
    int i = blockIdx.x * blockDim.x + threadIdx.x;
    if (i < EE) atomicAdd(&g_cnt[dst[i]], 1);
}
__global__ void scan_kernel() {
    __shared__ int ss[1024];
    int t = threadIdx.x;
    const int CH = (NN + 1023) / 1024;
    int base = t * CH;
    int loc = 0;
    for (int i = 0; i < CH; i++) {
        int idx = base + i;
        if (idx < NN) loc += g_cnt[idx];
    }
    ss[t] = loc;
    __syncthreads();
    for (int off = 1; off < 1024; off <<= 1) {
        int v = (t >= off) ? ss[t - off] : 0;
        __syncthreads();
        ss[t] += v;
        __syncthreads();
    }
    int run = (t == 0) ? 0 : ss[t - 1];
    for (int i = 0; i < CH; i++) {
        int idx = base + i;
        if (idx < NN) { g_rowptr[idx] = run; run += g_cnt[idx]; }
    }
    if (t == 0) g_rowptr[NN] = EE;
}
__global__ void scatter_kernel(const int* __restrict__ src, const int* __restrict__ dst,
                               const int* __restrict__ rid) {
    int i = blockIdx.x * blockDim.x + threadIdx.x;
    if (i < EE) {
        int d = dst[i];
        int pos = g_rowptr[d] + atomicAdd(&g_fill[d], 1);
        g_srcs[pos] = src[i];
        g_rids[pos] = rid[i];
    }
}

// ------------------------- edge attention + softmax ---------------------------
// one warp per dst node; fh/ftl live in g_proj (stride PF)
__global__ void attn_kernel(const float* __restrict__ attn) {
    int w = (blockIdx.x * blockDim.x + threadIdx.x) >> 5;
    int lane = threadIdx.x & 31;
    if (w >= NN) return;
    int node = w;
    float tl[HH], av[HH];
    #pragma unroll
    for (int h = 0; h < HH; h++) {
        tl[h] = g_proj[(size_t)node * PF + FF + h * DD + lane];
        av[h] = attn[h * DD + lane];
    }
    int beg = g_rowptr[node], end = g_rowptr[node + 1];
    float scale = logf((float)(end - beg)) * (1.0f / DD);
    for (int p = beg; p < end; p++) {
        int s = g_srcs[p], r = g_rids[p];
        const float* fhRow = g_proj + (size_t)s * PF;
        const float* frRow = g_fr + (size_t)r * FF;
        #pragma unroll
        for (int h = 0; h < HH; h++) {
            float x = fhRow[h * DD + lane] * tl[h] * frRow[h * DD + lane];
            x = (x > 0.f) ? x : SLOPE * x;
            float v = x * av[h];
            #pragma unroll
            for (int o = 16; o; o >>= 1) v += __shfl_xor_sync(0xffffffffu, v, o);
            if (lane == 0) g_e[p * HH + h] = v * scale;
        }
    }
    __syncwarp();
    if (lane < HH) {
        int h = lane;
        float m = -1e30f;
        for (int p = beg; p < end; p++) m = fmaxf(m, g_e[p * HH + h]);
        float ssum = 0.f;
        for (int p = beg; p < end; p++) ssum += expf(g_e[p * HH + h] - m);
        float inv = 1.0f / ssum;
        for (int p = beg; p < end; p++) g_a[p * HH + h] = expf(g_e[p * HH + h] - m) * inv;
    }
}

// ------------------------- diffusion hop --------------------------------------
__global__ void hop_kernel(const float* __restrict__ fin, int fstride,
                           float* __restrict__ fout, const float* __restrict__ ent) {
    int w = (blockIdx.x * blockDim.x + threadIdx.x) >> 5;
    int lane = threadIdx.x & 31;
    if (w >= NN) return;
    int node = w;
    int beg = g_rowptr[node], end = g_rowptr[node + 1];
    float acc[HH];
    #pragma unroll
    for (int h = 0; h < HH; h++) acc[h] = 0.f;
    for (int p = beg; p < end; p++) {
        int s = g_srcs[p];
        const float* frow = fin + (size_t)s * fstride;
        #pragma unroll
        for (int h = 0; h < HH; h++)
            acc[h] += g_a[p * HH + h] * frow[h * DD + lane];
    }
    const float* f0 = g_proj + (size_t)node * PF + 2 * FF;
    #pragma unroll
    for (int h = 0; h < HH; h++) {
        int cc = h * DD + lane;
        float v = (1.0f - ALPHA) * acc[h] + ALPHA * f0[cc];
        if (ent) v += ent[node * FF + cc];
        fout[(size_t)node * FF + cc] = v;
    }
}

// ------------------------- launcher -------------------------------------------
extern "C" void kernel_launch(void* const* d_in, const int* in_sizes, int n_in,
                              void* d_out, int out_size) {
    const float* ent_feat = (const float*)d_in[0];
    const float* rel_feat = (const float*)d_in[1];
    const float* W_head   = (const float*)d_in[2];
    const float* W_tail   = (const float*)d_in[3];
    const float* W_ent    = (const float*)d_in[4];
    const float* W_rel    = (const float*)d_in[5];
    const float* attn     = (const float*)d_in[6];
    const float* ln_ent_g = (const float*)d_in[7];
    const float* ln_ent_b = (const float*)d_in[8];
    const float* ln_rel_g = (const float*)d_in[9];
    const float* ln_rel_b = (const float*)d_in[10];
    const float* ln_ff_g  = (const float*)d_in[11];
    const float* ln_ff_b  = (const float*)d_in[12];
    const float* W1       = (const float*)d_in[13];
    const float* b1       = (const float*)d_in[14];
    const float* W2       = (const float*)d_in[15];
    const float* b2       = (const float*)d_in[16];
    const int*   src      = (const int*)d_in[17];
    const int*   dst      = (const int*)d_in[18];
    const int*   rid      = (const int*)d_in[19];
    float* out = (float*)d_out;

    cudaFuncSetAttribute(mma_gemm, cudaFuncAttributeMaxDynamicSharedMemorySize, GSMEM_BYTES);

    float *xln, *proj, *rln, *fr, *fa, *fb, *rst, *y, *hid, *wcat, *wrel, *w1T, *w2T;
    cudaGetSymbolAddress((void**)&xln,  g_xln);
    cudaGetSymbolAddress((void**)&proj, g_proj);
    cudaGetSymbolAddress((void**)&rln,  g_rln);
    cudaGetSymbolAddress((void**)&fr,   g_fr);
    cudaGetSymbolAddress((void**)&fa,   g_fa);
    cudaGetSymbolAddress((void**)&fb,   g_fb);
    cudaGetSymbolAddress((void**)&rst,  g_rst);
    cudaGetSymbolAddress((void**)&y,    g_y);
    cudaGetSymbolAddress((void**)&hid,  g_hid);
    cudaGetSymbolAddress((void**)&wcat, g_wcatT);
    cudaGetSymbolAddress((void**)&wrel, g_wrelT);
    cudaGetSymbolAddress((void**)&w1T,  g_w1T);
    cudaGetSymbolAddress((void**)&w2T,  g_w2T);

    // 0) transpose + tf32-round weights
    dim3 tb(32, 8);
    transpose4_rnd<<<dim3(FF / 32, FF / 32, 4), tb>>>(W_head, W_tail, W_ent, W_rel, wcat, wrel);
    transpose_rnd<<<dim3(FHID / 32, FF / 32), tb>>>(W1, w1T, FF, FHID);
    transpose_rnd<<<dim3(FF / 32, FHID / 32), tb>>>(W2, w2T, FHID, FF);

    // 1) LayerNorms (tf32-rounded outputs; only consumed by GEMMs)
    ln_kernel<<<NN, 256>>>(ent_feat, xln, ln_ent_g, ln_ent_b);
    ln_kernel<<<RR, 256>>>(rel_feat, rln, ln_rel_g, ln_rel_b);

    // 2) Projections: rel + fused head/tail/ent (Nc=768)
    const int mT = (NN + 127) / 128;   // 157
    mma_gemm<<<dim3(FF / 128, 1), 128, GSMEM_BYTES>>>(rln, wrel, fr, RR, FF, FF, nullptr, nullptr, 0);
    mma_gemm<<<dim3(PF / 128, mT), 128, GSMEM_BYTES>>>(xln, wcat, proj, NN, PF, FF, nullptr, nullptr, 0);

    // 3) CSR build (sorted by dst)
    zero_kernel<<<(NN + 255) / 256, 256>>>();
    count_kernel<<<(EE + 255) / 256, 256>>>(dst);
    scan_kernel<<<1, 1024>>>();
    scatter_kernel<<<(EE + 255) / 256, 256>>>(src, dst, rid);

    // 4) edge attention + per-node softmax
    attn_kernel<<<NN / 8, 256>>>(attn);

    // 5) 5 PPR hops (ping-pong), last adds ent_feat residual -> g_rst
    hop_kernel<<<NN / 8, 256>>>(proj + 2 * FF, PF, fa, nullptr);
    hop_kernel<<<NN / 8, 256>>>(fa, FF, fb, nullptr);
    hop_kernel<<<NN / 8, 256>>>(fb, FF, fa, nullptr);
    hop_kernel<<<NN / 8, 256>>>(fa, FF, fb, nullptr);
    hop_kernel<<<NN / 8, 256>>>(fb, FF, rst, ent_feat);

    // 6) FFN with pre-LN and residual
    ln_kernel<<<NN, 256>>>(rst, y, ln_ff_g, ln_ff_b);
    mma_gemm<<<dim3(FHID / 128, mT), 128, GSMEM_BYTES>>>(y, w1T, hid, NN, FHID, FF, b1, nullptr, 1 | 2);
    mma_gemm<<<dim3(FF / 128, mT), 128, GSMEM_BYTES>>>(hid, w2T, out, NN, FF, FHID, b2, rst, 0);
}